// round 1
// baseline (speedup 1.0000x reference)
#include <cuda_runtime.h>
#include <math.h>

#define S_LEN 4096
#define B_SZ  64
#define EMB   128
#define DEC   128
#define FANIN (EMB + DEC)
#define PAD   132   // floats; keeps float4 alignment (132*4 % 16 == 0) and bank spread (132%32==4)

// Scratch (no device allocation allowed)
__device__ float g_hproj[B_SZ * DEC];
__device__ float g_scores[B_SZ * S_LEN];   // [b][s]

// ---------------------------------------------------------------------------
// Kernel A: h_proj[b][d] = sum_e hidden[b][e] * W_attn[d][e] + b_attn[d]
// ---------------------------------------------------------------------------
__global__ void hproj_kernel(const float* __restrict__ hidden,
                             const float* __restrict__ W,
                             const float* __restrict__ bias) {
    __shared__ float h[DEC];
    int b = blockIdx.x, d = threadIdx.x;
    h[d] = hidden[b * DEC + d];
    __syncthreads();
    float acc = bias[d];
    const float* w = W + d * FANIN;   // Wh row d = first 128 cols
    #pragma unroll 8
    for (int e = 0; e < DEC; e++) acc = fmaf(h[e], w[e], acc);
    g_hproj[b * DEC + d] = acc;
}

// ---------------------------------------------------------------------------
// Kernel B: for s = blockIdx.x, rows m = s*64 + b (contiguous in seq_embs):
//   y[b][d] = h_proj[b][d] + sum_e X[b][e] * We[d][e]
//   score[b][s] = sum_d v[d] * tanh(y[b][d])
// 256 threads: tid = y*16 + x; thread owns rows {4y..4y+3} x cols {x+16j, j<8}
// ---------------------------------------------------------------------------
extern __shared__ float smem[];

__global__ __launch_bounds__(256) void score_kernel(const float* __restrict__ seq,
                                                    const float* __restrict__ W,
                                                    const float* __restrict__ vw) {
    float* xs = smem;                         // 64  * PAD
    float* ws = smem + B_SZ * PAD;            // 128 * PAD
    float* vs = smem + (B_SZ + DEC) * PAD;    // 128

    const int tid = threadIdx.x;
    const int s   = blockIdx.x;

    // Stage We[d][e] = W_attn[d][128 + e]  (128x128 f32)
    for (int idx = tid; idx < DEC * EMB / 4; idx += 256) {
        int d  = idx >> 5;            // /32
        int e4 = (idx & 31) << 2;     // 4-float column chunk
        float4 v = *(const float4*)(W + d * FANIN + DEC + e4);
        *(float4*)(ws + d * PAD + e4) = v;
    }
    // Stage X tile: seq_embs rows [s*64 .. s*64+63], contiguous 32KB
    {
        const float4* src = (const float4*)(seq + (size_t)s * B_SZ * EMB);
        for (int idx = tid; idx < B_SZ * EMB / 4; idx += 256) {
            float4 v = src[idx];
            int flat = idx << 2;
            int r = flat >> 7;        // /128
            int e = flat & 127;
            *(float4*)(xs + r * PAD + e) = v;
        }
    }
    if (tid < DEC) vs[tid] = vw[tid];
    __syncthreads();

    const int x = tid & 15;
    const int y = tid >> 4;

    // Accumulators initialized with h_proj (folds the bias-add into the GEMM)
    float acc[4][8];
    #pragma unroll
    for (int i = 0; i < 4; i++)
        #pragma unroll
        for (int j = 0; j < 8; j++)
            acc[i][j] = g_hproj[(y * 4 + i) * DEC + (x + 16 * j)];

    // Main K loop: 128 FFMA per 12 LDS.128 per thread
    #pragma unroll 2
    for (int e = 0; e < EMB; e += 4) {
        float4 a[4], w[8];
        #pragma unroll
        for (int i = 0; i < 4; i++) a[i] = *(float4*)(xs + (y * 4 + i) * PAD + e);
        #pragma unroll
        for (int j = 0; j < 8; j++) w[j] = *(float4*)(ws + (x + 16 * j) * PAD + e);
        #pragma unroll
        for (int i = 0; i < 4; i++)
            #pragma unroll
            for (int j = 0; j < 8; j++) {
                acc[i][j] = fmaf(a[i].x, w[j].x, acc[i][j]);
                acc[i][j] = fmaf(a[i].y, w[j].y, acc[i][j]);
                acc[i][j] = fmaf(a[i].z, w[j].z, acc[i][j]);
                acc[i][j] = fmaf(a[i].w, w[j].w, acc[i][j]);
            }
    }

    // Epilogue: tanh, dot with v, reduce across the 16 x-lanes of each row
    #pragma unroll
    for (int i = 0; i < 4; i++) {
        float p = 0.f;
        #pragma unroll
        for (int j = 0; j < 8; j++)
            p += vs[x + 16 * j] * tanhf(acc[i][j]);
        #pragma unroll
        for (int off = 8; off > 0; off >>= 1)
            p += __shfl_down_sync(0xffffffffu, p, off, 16);
        if (x == 0)
            g_scores[(y * 4 + i) * S_LEN + s] = p;   // scores[b][s]
    }
}

// ---------------------------------------------------------------------------
// Kernel C: masked softmax over s for each b
// ---------------------------------------------------------------------------
__global__ __launch_bounds__(256) void softmax_kernel(const int* __restrict__ mask,
                                                      float* __restrict__ out) {
    __shared__ float red[256];
    const int b = blockIdx.x, tid = threadIdx.x;
    const float* sc = g_scores + b * S_LEN;
    const int*   mk = mask + b * S_LEN;

    float mx = -1e30f;
    for (int s = tid; s < S_LEN; s += 256) {
        float v = (mk[s] == 0) ? -1e10f : sc[s];
        mx = fmaxf(mx, v);
    }
    red[tid] = mx; __syncthreads();
    for (int o = 128; o > 0; o >>= 1) {
        if (tid < o) red[tid] = fmaxf(red[tid], red[tid + o]);
        __syncthreads();
    }
    mx = red[0]; __syncthreads();

    float sum = 0.f;
    for (int s = tid; s < S_LEN; s += 256) {
        float v = (mk[s] == 0) ? -1e10f : sc[s];
        sum += expf(v - mx);
    }
    red[tid] = sum; __syncthreads();
    for (int o = 128; o > 0; o >>= 1) {
        if (tid < o) red[tid] += red[tid + o];
        __syncthreads();
    }
    float inv = 1.f / red[0];

    for (int s = tid; s < S_LEN; s += 256) {
        float v = (mk[s] == 0) ? -1e10f : sc[s];
        out[b * S_LEN + s] = expf(v - mx) * inv;
    }
}

// ---------------------------------------------------------------------------
// Inputs (metadata order): hidden(64*128) f32, seq_embs(4096*64*128) f32,
// mask(64*4096) i32, W_attn(128*256) f32, b_attn(128) f32, v_w(128) f32.
// Output: (64,4096) f32.
// ---------------------------------------------------------------------------
extern "C" void kernel_launch(void* const* d_in, const int* in_sizes, int n_in,
                              void* d_out, int out_size) {
    const float* hidden = (const float*)d_in[0];
    const float* seq    = (const float*)d_in[1];
    const int*   mask   = (const int*)d_in[2];
    const float* W      = (const float*)d_in[3];
    const float* bias   = (const float*)d_in[4];
    const float* vw     = (const float*)d_in[5];
    float* out = (float*)d_out;

    const int smem_bytes = (B_SZ + DEC) * PAD * (int)sizeof(float) + DEC * (int)sizeof(float);
    cudaFuncSetAttribute(score_kernel, cudaFuncAttributeMaxDynamicSharedMemorySize, smem_bytes);

    hproj_kernel<<<B_SZ, DEC>>>(hidden, W, bias);
    score_kernel<<<S_LEN, 256, smem_bytes>>>(seq, W, vw);
    softmax_kernel<<<B_SZ, 256>>>(mask, out);
}

// round 3
// speedup vs baseline: 1.4716x; 1.4716x over previous
#include <cuda_runtime.h>
#include <cuda_bf16.h>
#include <math.h>
#include <stdint.h>

#define S_LEN 4096
#define B_SZ  64
#define EMB   128
#define DEC   128
#define FANIN 256
#define LDW   68            // u32 words per bf16 row: 136 bf16 = 128 data + 8 pad
#define ROWB  272           // bytes per padded bf16 row

// ---------------- scratch (no device allocation allowed) ----------------
__device__ float g_hproj[B_SZ * DEC];
__device__ float g_scores[B_SZ * S_LEN];
__device__ __align__(16) uint32_t g_we_hi[128 * LDW];   // We hi bf16, [n][k] padded
__device__ __align__(16) uint32_t g_we_lo[128 * LDW];   // We lo bf16

// ---------------- helpers ----------------
__device__ __forceinline__ uint32_t smem_u32(const void* p) {
    uint32_t a;
    asm("{ .reg .u64 t; cvta.to.shared.u64 t, %1; cvt.u32.u64 %0, t; }" : "=r"(a) : "l"(p));
    return a;
}
#define LDSM4(r, a) \
    asm volatile("ldmatrix.sync.aligned.m8n8.x4.shared.b16 {%0,%1,%2,%3}, [%4];" \
        : "=r"((r)[0]), "=r"((r)[1]), "=r"((r)[2]), "=r"((r)[3]) : "r"(a))

#define MMA16816(c, a, b0, b1) \
    asm volatile("mma.sync.aligned.m16n8k16.row.col.f32.bf16.bf16.f32 " \
        "{%0,%1,%2,%3},{%4,%5,%6,%7},{%8,%9},{%0,%1,%2,%3};" \
        : "+f"((c)[0]), "+f"((c)[1]), "+f"((c)[2]), "+f"((c)[3]) \
        : "r"((a)[0]), "r"((a)[1]), "r"((a)[2]), "r"((a)[3]), "r"(b0), "r"(b1))

__device__ __forceinline__ float fast_tanh(float x) {
    float e = __expf(2.0f * x);
    return 1.0f - 2.0f / (e + 1.0f);
}

// ---------------------------------------------------------------------------
// h_proj[b][d] = hidden[b] . Wh[d] + b_attn[d]
// ---------------------------------------------------------------------------
__global__ void hproj_kernel(const float* __restrict__ hidden,
                             const float* __restrict__ W,
                             const float* __restrict__ bias) {
    __shared__ float h[DEC];
    int b = blockIdx.x, d = threadIdx.x;
    h[d] = hidden[b * DEC + d];
    __syncthreads();
    float acc = bias[d];
    const float* w = W + d * FANIN;
    #pragma unroll 8
    for (int e = 0; e < DEC; e++) acc = fmaf(h[e], w[e], acc);
    g_hproj[b * DEC + d] = acc;
}

// ---------------------------------------------------------------------------
// Split We (cols 128..255 of W_attn) into bf16 hi/lo, padded [n][136] layout
// ---------------------------------------------------------------------------
__global__ void wsplit_kernel(const float* __restrict__ W) {
    int idx = blockIdx.x * 256 + threadIdx.x;   // 128*64 = 8192 bf16x2 words
    int n  = idx >> 6;
    int kp = idx & 63;
    float x0 = W[n * FANIN + DEC + 2 * kp];
    float x1 = W[n * FANIN + DEC + 2 * kp + 1];
    uint32_t hi, lo;
    asm("cvt.rn.bf16x2.f32 %0, %1, %2;" : "=r"(hi) : "f"(x1), "f"(x0));  // x0 low half
    float e0 = x0 - __uint_as_float(hi << 16);
    float e1 = x1 - __uint_as_float(hi & 0xffff0000u);
    asm("cvt.rn.bf16x2.f32 %0, %1, %2;" : "=r"(lo) : "f"(e1), "f"(e0));
    g_we_hi[n * LDW + kp] = hi;
    g_we_lo[n * LDW + kp] = lo;
}

// ---------------------------------------------------------------------------
// score kernel: one CTA per s. mma.sync bf16 3-product split GEMM + epilogue.
// ---------------------------------------------------------------------------
#define OFF_V    0
#define OFF_PART 512
#define OFF_BHI  1024
#define OFF_BLO  (OFF_BHI + 34816)
#define OFF_XHI  (OFF_BLO + 34816)
#define OFF_XLO  (OFF_XHI + 17408)
#define SMEM_BYTES (OFF_XLO + 17408)   // 105472

extern __shared__ char smem[];

__global__ __launch_bounds__(256) void score_kernel(const float* __restrict__ seq,
                                                    const float* __restrict__ vw) {
    const int tid  = threadIdx.x;
    const int wid  = tid >> 5;
    const int lane = tid & 31;
    const int s    = blockIdx.x;

    // ---- stage We hi/lo (already in padded layout) and v ----
    {
        const int4* sh = (const int4*)g_we_hi;
        const int4* sl = (const int4*)g_we_lo;
        int4* dh = (int4*)(smem + OFF_BHI);
        int4* dl = (int4*)(smem + OFF_BLO);
        for (int i = tid; i < 2176; i += 256) { dh[i] = sh[i]; dl[i] = sl[i]; }
    }
    if (tid < 128) ((float*)(smem + OFF_V))[tid] = vw[tid];

    // ---- load X tile (64x128 f32, contiguous), split to bf16 hi/lo ----
    {
        const float4* src = (const float4*)(seq + (size_t)s * B_SZ * EMB);
        for (int i = tid; i < 2048; i += 256) {
            float4 x = src[i];
            int row = i >> 5, c4 = i & 31;
            uint32_t h0, h1, l0, l1;
            asm("cvt.rn.bf16x2.f32 %0, %1, %2;" : "=r"(h0) : "f"(x.y), "f"(x.x));
            asm("cvt.rn.bf16x2.f32 %0, %1, %2;" : "=r"(h1) : "f"(x.w), "f"(x.z));
            float e0 = x.x - __uint_as_float(h0 << 16);
            float e1 = x.y - __uint_as_float(h0 & 0xffff0000u);
            float e2 = x.z - __uint_as_float(h1 << 16);
            float e3 = x.w - __uint_as_float(h1 & 0xffff0000u);
            asm("cvt.rn.bf16x2.f32 %0, %1, %2;" : "=r"(l0) : "f"(e1), "f"(e0));
            asm("cvt.rn.bf16x2.f32 %0, %1, %2;" : "=r"(l1) : "f"(e3), "f"(e2));
            char* px = smem + OFF_XHI + row * ROWB + c4 * 8;
            *(uint2*)px = make_uint2(h0, h1);
            *(uint2*)(px + 17408) = make_uint2(l0, l1);
        }
    }
    __syncthreads();

    // ---- warp tile: m-tile (wid&3)*16, n-half (wid>>2)*64 ----
    const int mbase = (wid & 3) * 16;
    const int nbase = (wid >> 2) * 64;
    const int j = lane >> 3, r = lane & 7;

    // ldmatrix lane addresses (x4: mat j -> rows from lanes 8j..8j+7)
    // A: mat0 m0-7/k0-7, mat1 m8-15/k0-7, mat2 m0-7/k8-15, mat3 m8-15/k8-15
    uint32_t a_hi = smem_u32(smem + OFF_XHI)
                  + (uint32_t)(mbase + r + 8 * (j & 1)) * ROWB + (uint32_t)(j >> 1) * 16;
    uint32_t a_lo = a_hi + 17408;
    // B: mat0 nt0/k0-7, mat1 nt0/k8-15, mat2 nt1/k0-7, mat3 nt1/k8-15
    uint32_t b_hi = smem_u32(smem + OFF_BHI)
                  + (uint32_t)(nbase + (j >> 1) * 8 + r) * ROWB + (uint32_t)(j & 1) * 16;
    uint32_t b_lo = b_hi + 34816;

    float acc[8][4];
    #pragma unroll
    for (int nt = 0; nt < 8; nt++)
        #pragma unroll
        for (int q = 0; q < 4; q++) acc[nt][q] = 0.f;

    #pragma unroll
    for (int k = 0; k < 8; k++) {
        uint32_t ah[4], al[4];
        LDSM4(ah, a_hi + k * 32);
        LDSM4(al, a_lo + k * 32);
        #pragma unroll
        for (int p = 0; p < 4; p++) {
            uint32_t bh[4], bl[4];
            uint32_t boff = (uint32_t)p * (16 * ROWB) + (uint32_t)k * 32;
            LDSM4(bh, b_hi + boff);
            LDSM4(bl, b_lo + boff);
            MMA16816(acc[2 * p],     ah, bh[0], bh[1]);
            MMA16816(acc[2 * p],     ah, bl[0], bl[1]);
            MMA16816(acc[2 * p],     al, bh[0], bh[1]);
            MMA16816(acc[2 * p + 1], ah, bh[2], bh[3]);
            MMA16816(acc[2 * p + 1], ah, bl[2], bl[3]);
            MMA16816(acc[2 * p + 1], al, bh[2], bh[3]);
        }
    }
    __syncthreads();

    // ---- stage h_proj (broadcast 64x128 f32) into the freed X region ----
    {
        float4* dst = (float4*)(smem + OFF_XHI);
        const float4* src = (const float4*)g_hproj;
        for (int i = tid; i < 2048; i += 256) dst[i] = src[i];
    }
    __syncthreads();

    // ---- epilogue: tanh + v-dot + reduce ----
    const float* hp = (const float*)(smem + OFF_XHI);
    const float* vs = (const float*)(smem + OFF_V);
    const int q  = lane & 3;
    const int r0 = mbase + (lane >> 2), r1 = r0 + 8;

    float p0 = 0.f, p1 = 0.f;
    #pragma unroll
    for (int nt = 0; nt < 8; nt++) {
        int c0 = nbase + nt * 8 + 2 * q;
        float v0 = vs[c0], v1 = vs[c0 + 1];
        p0 = fmaf(v0, fast_tanh(acc[nt][0] + hp[r0 * 128 + c0]), p0);
        p0 = fmaf(v1, fast_tanh(acc[nt][1] + hp[r0 * 128 + c0 + 1]), p0);
        p1 = fmaf(v0, fast_tanh(acc[nt][2] + hp[r1 * 128 + c0]), p1);
        p1 = fmaf(v1, fast_tanh(acc[nt][3] + hp[r1 * 128 + c0 + 1]), p1);
    }
    p0 += __shfl_xor_sync(0xffffffffu, p0, 1);
    p0 += __shfl_xor_sync(0xffffffffu, p0, 2);
    p1 += __shfl_xor_sync(0xffffffffu, p1, 1);
    p1 += __shfl_xor_sync(0xffffffffu, p1, 2);

    float* part = (float*)(smem + OFF_PART);
    if (q == 0) {
        part[(wid >> 2) * 64 + r0] = p0;
        part[(wid >> 2) * 64 + r1] = p1;
    }
    __syncthreads();
    if (tid < 64)
        g_scores[tid * S_LEN + s] = part[tid] + part[64 + tid];
}

// ---------------------------------------------------------------------------
// masked softmax over s per batch row
// ---------------------------------------------------------------------------
__global__ __launch_bounds__(256) void softmax_kernel(const int* __restrict__ mask,
                                                      float* __restrict__ out) {
    __shared__ float red[256];
    const int b = blockIdx.x, tid = threadIdx.x;
    const float* sc = g_scores + b * S_LEN;
    const int*   mk = mask + b * S_LEN;

    float mx = -1e30f;
    for (int s = tid; s < S_LEN; s += 256) {
        float v = (mk[s] == 0) ? -1e10f : sc[s];
        mx = fmaxf(mx, v);
    }
    red[tid] = mx; __syncthreads();
    for (int o = 128; o > 0; o >>= 1) {
        if (tid < o) red[tid] = fmaxf(red[tid], red[tid + o]);
        __syncthreads();
    }
    mx = red[0]; __syncthreads();

    float sum = 0.f;
    for (int s = tid; s < S_LEN; s += 256) {
        float v = (mk[s] == 0) ? -1e10f : sc[s];
        sum += expf(v - mx);
    }
    red[tid] = sum; __syncthreads();
    for (int o = 128; o > 0; o >>= 1) {
        if (tid < o) red[tid] += red[tid + o];
        __syncthreads();
    }
    float inv = 1.f / red[0];

    for (int s = tid; s < S_LEN; s += 256) {
        float v = (mk[s] == 0) ? -1e10f : sc[s];
        out[b * S_LEN + s] = expf(v - mx) * inv;
    }
}

// ---------------------------------------------------------------------------
extern "C" void kernel_launch(void* const* d_in, const int* in_sizes, int n_in,
                              void* d_out, int out_size) {
    const float* hidden = (const float*)d_in[0];
    const float* seq    = (const float*)d_in[1];
    const int*   mask   = (const int*)d_in[2];
    const float* W      = (const float*)d_in[3];
    const float* bias   = (const float*)d_in[4];
    const float* vw     = (const float*)d_in[5];
    float* out = (float*)d_out;

    cudaFuncSetAttribute(score_kernel, cudaFuncAttributeMaxDynamicSharedMemorySize, SMEM_BYTES);

    hproj_kernel<<<B_SZ, DEC>>>(hidden, W, bias);
    wsplit_kernel<<<32, 256>>>(W);
    score_kernel<<<S_LEN, 256, SMEM_BYTES>>>(seq, vw);
    softmax_kernel<<<B_SZ, 256>>>(mask, out);
}

// round 4
// speedup vs baseline: 2.6741x; 1.8171x over previous
#include <cuda_runtime.h>
#include <cuda_bf16.h>
#include <math.h>
#include <stdint.h>

#define S_LEN 4096
#define B_SZ  64
#define EMB   128
#define DEC   128
#define FANIN 256
#define LDW   68            // u32 words per bf16 row: 136 bf16 = 128 data + 8 pad
#define ROWB  272           // bytes per padded bf16 row
#define NCTA  296           // persistent grid: 2 CTAs/SM x 148 SMs

// ---------------- scratch (no device allocation allowed) ----------------
__device__ float g_hproj[B_SZ * DEC];
__device__ float g_scores[B_SZ * S_LEN];
__device__ __align__(16) uint32_t g_we_hi[128 * LDW];   // We hi bf16, [n][k] padded
__device__ __align__(16) uint32_t g_we_lo[128 * LDW];   // We lo bf16

// ---------------- helpers ----------------
__device__ __forceinline__ uint32_t smem_u32(const void* p) {
    uint32_t a;
    asm("{ .reg .u64 t; cvta.to.shared.u64 t, %1; cvt.u32.u64 %0, t; }" : "=r"(a) : "l"(p));
    return a;
}
#define LDSM4(r, a) \
    asm volatile("ldmatrix.sync.aligned.m8n8.x4.shared.b16 {%0,%1,%2,%3}, [%4];" \
        : "=r"((r)[0]), "=r"((r)[1]), "=r"((r)[2]), "=r"((r)[3]) : "r"(a))

#define MMA16816(c, a, b0, b1) \
    asm volatile("mma.sync.aligned.m16n8k16.row.col.f32.bf16.bf16.f32 " \
        "{%0,%1,%2,%3},{%4,%5,%6,%7},{%8,%9},{%0,%1,%2,%3};" \
        : "+f"((c)[0]), "+f"((c)[1]), "+f"((c)[2]), "+f"((c)[3]) \
        : "r"((a)[0]), "r"((a)[1]), "r"((a)[2]), "r"((a)[3]), "r"(b0), "r"(b1))

__device__ __forceinline__ float fast_tanh(float x) {
    float e = __expf(2.0f * x);
    return 1.0f - 2.0f / (e + 1.0f);
}

// ---------------------------------------------------------------------------
// h_proj[b][d] = hidden[b] . Wh[d] + b_attn[d]   (coalesced warp-per-row)
// ---------------------------------------------------------------------------
__global__ __launch_bounds__(256) void hproj_kernel(const float* __restrict__ hidden,
                                                    const float* __restrict__ W,
                                                    const float* __restrict__ bias) {
    __shared__ float h[DEC];
    const int b = blockIdx.x, tid = threadIdx.x;
    const int wid = tid >> 5, lane = tid & 31;
    if (tid < DEC) h[tid] = hidden[b * DEC + tid];
    __syncthreads();
    #pragma unroll
    for (int i = 0; i < 16; i++) {
        int d = wid * 16 + i;
        const float* w = W + d * FANIN;
        float sum = 0.f;
        #pragma unroll
        for (int e = lane; e < DEC; e += 32) sum = fmaf(h[e], w[e], sum);
        #pragma unroll
        for (int o = 16; o > 0; o >>= 1) sum += __shfl_xor_sync(0xffffffffu, sum, o);
        if (lane == 0) g_hproj[b * DEC + d] = sum + bias[d];
    }
}

// ---------------------------------------------------------------------------
// Split We (cols 128..255 of W_attn) into bf16 hi/lo, padded [n][136] layout
// ---------------------------------------------------------------------------
__global__ void wsplit_kernel(const float* __restrict__ W) {
    int idx = blockIdx.x * 256 + threadIdx.x;   // 128*64 = 8192 bf16x2 words
    int n  = idx >> 6;
    int kp = idx & 63;
    float x0 = W[n * FANIN + DEC + 2 * kp];
    float x1 = W[n * FANIN + DEC + 2 * kp + 1];
    uint32_t hi, lo;
    asm("cvt.rn.bf16x2.f32 %0, %1, %2;" : "=r"(hi) : "f"(x1), "f"(x0));  // x0 low half
    float e0 = x0 - __uint_as_float(hi << 16);
    float e1 = x1 - __uint_as_float(hi & 0xffff0000u);
    asm("cvt.rn.bf16x2.f32 %0, %1, %2;" : "=r"(lo) : "f"(e1), "f"(e0));
    g_we_hi[n * LDW + kp] = hi;
    g_we_lo[n * LDW + kp] = lo;
}

// ---------------------------------------------------------------------------
// persistent score kernel: 296 CTAs, grid-stride over s.
// We/v staged once; h_proj held in registers; per-tile: load/convert X,
// 3-product bf16 mma.sync GEMM, tanh+v-dot epilogue.
// ---------------------------------------------------------------------------
#define OFF_V    0
#define OFF_PART 512
#define OFF_BHI  1024
#define OFF_BLO  (OFF_BHI + 34816)
#define OFF_XHI  (OFF_BLO + 34816)
#define OFF_XLO  (OFF_XHI + 17408)
#define SMEM_BYTES (OFF_XLO + 17408)   // 105472

extern __shared__ char smem[];

__global__ __launch_bounds__(256, 2) void score_kernel(const float* __restrict__ seq,
                                                       const float* __restrict__ vw) {
    const int tid  = threadIdx.x;
    const int wid  = tid >> 5;
    const int lane = tid & 31;

    // ---- one-time staging: We hi/lo + v ----
    {
        const int4* sh = (const int4*)g_we_hi;
        const int4* sl = (const int4*)g_we_lo;
        int4* dh = (int4*)(smem + OFF_BHI);
        int4* dl = (int4*)(smem + OFF_BLO);
        for (int i = tid; i < 2176; i += 256) { dh[i] = sh[i]; dl[i] = sl[i]; }
    }
    if (tid < 128) ((float*)(smem + OFF_V))[tid] = vw[tid];

    // ---- loop-invariant per-thread state ----
    const int mbase = (wid & 3) * 16;
    const int nbase = (wid >> 2) * 64;
    const int j = lane >> 3, r = lane & 7;
    const int q  = lane & 3;
    const int r0 = mbase + (lane >> 2), r1 = r0 + 8;

    // h_proj values this thread needs (fixed rows/cols) -> registers
    float hpA[8][2], hpB[8][2];
    #pragma unroll
    for (int nt = 0; nt < 8; nt++) {
        int c0 = nbase + nt * 8 + 2 * q;
        hpA[nt][0] = g_hproj[r0 * DEC + c0];
        hpA[nt][1] = g_hproj[r0 * DEC + c0 + 1];
        hpB[nt][0] = g_hproj[r1 * DEC + c0];
        hpB[nt][1] = g_hproj[r1 * DEC + c0 + 1];
    }

    // ldmatrix lane addresses (loop-invariant)
    const uint32_t a_hi = smem_u32(smem + OFF_XHI)
                        + (uint32_t)(mbase + r + 8 * (j & 1)) * ROWB + (uint32_t)(j >> 1) * 16;
    const uint32_t a_lo = a_hi + 17408;
    const uint32_t b_hi = smem_u32(smem + OFF_BHI)
                        + (uint32_t)(nbase + (j >> 1) * 8 + r) * ROWB + (uint32_t)(j & 1) * 16;
    const uint32_t b_lo = b_hi + 34816;

    float* part = (float*)(smem + OFF_PART);
    const float* vs = (const float*)(smem + OFF_V);
    __syncthreads();

    for (int s = blockIdx.x; s < S_LEN; s += NCTA) {
        // ---- load X tile (64x128 f32), split to bf16 hi/lo in smem ----
        const float4* src = (const float4*)(seq + (size_t)s * B_SZ * EMB);
        #pragma unroll
        for (int ii = 0; ii < 8; ii++) {
            int i = tid + ii * 256;
            float4 x = src[i];
            int row = i >> 5, c4 = i & 31;
            uint32_t h0, h1, l0, l1;
            asm("cvt.rn.bf16x2.f32 %0, %1, %2;" : "=r"(h0) : "f"(x.y), "f"(x.x));
            asm("cvt.rn.bf16x2.f32 %0, %1, %2;" : "=r"(h1) : "f"(x.w), "f"(x.z));
            float e0 = x.x - __uint_as_float(h0 << 16);
            float e1 = x.y - __uint_as_float(h0 & 0xffff0000u);
            float e2 = x.z - __uint_as_float(h1 << 16);
            float e3 = x.w - __uint_as_float(h1 & 0xffff0000u);
            asm("cvt.rn.bf16x2.f32 %0, %1, %2;" : "=r"(l0) : "f"(e1), "f"(e0));
            asm("cvt.rn.bf16x2.f32 %0, %1, %2;" : "=r"(l1) : "f"(e3), "f"(e2));
            char* px = smem + OFF_XHI + row * ROWB + c4 * 8;
            *(uint2*)px = make_uint2(h0, h1);
            *(uint2*)(px + 17408) = make_uint2(l0, l1);
        }
        __syncthreads();

        // ---- GEMM: D = Ahi*Bhi + Ahi*Blo + Alo*Bhi ----
        float acc[8][4];
        #pragma unroll
        for (int nt = 0; nt < 8; nt++)
            #pragma unroll
            for (int qq = 0; qq < 4; qq++) acc[nt][qq] = 0.f;

        #pragma unroll
        for (int k = 0; k < 8; k++) {
            uint32_t ah[4], al[4];
            LDSM4(ah, a_hi + k * 32);
            LDSM4(al, a_lo + k * 32);
            #pragma unroll
            for (int p = 0; p < 4; p++) {
                uint32_t bh[4], bl[4];
                uint32_t boff = (uint32_t)p * (16 * ROWB) + (uint32_t)k * 32;
                LDSM4(bh, b_hi + boff);
                LDSM4(bl, b_lo + boff);
                MMA16816(acc[2 * p],     ah, bh[0], bh[1]);
                MMA16816(acc[2 * p],     ah, bl[0], bl[1]);
                MMA16816(acc[2 * p],     al, bh[0], bh[1]);
                MMA16816(acc[2 * p + 1], ah, bh[2], bh[3]);
                MMA16816(acc[2 * p + 1], ah, bl[2], bl[3]);
                MMA16816(acc[2 * p + 1], al, bh[2], bh[3]);
            }
        }

        // ---- epilogue: tanh + v-dot + quad reduce ----
        float p0 = 0.f, p1 = 0.f;
        #pragma unroll
        for (int nt = 0; nt < 8; nt++) {
            int c0 = nbase + nt * 8 + 2 * q;
            float v0 = vs[c0], v1 = vs[c0 + 1];
            p0 = fmaf(v0, fast_tanh(acc[nt][0] + hpA[nt][0]), p0);
            p0 = fmaf(v1, fast_tanh(acc[nt][1] + hpA[nt][1]), p0);
            p1 = fmaf(v0, fast_tanh(acc[nt][2] + hpB[nt][0]), p1);
            p1 = fmaf(v1, fast_tanh(acc[nt][3] + hpB[nt][1]), p1);
        }
        p0 += __shfl_xor_sync(0xffffffffu, p0, 1);
        p0 += __shfl_xor_sync(0xffffffffu, p0, 2);
        p1 += __shfl_xor_sync(0xffffffffu, p1, 1);
        p1 += __shfl_xor_sync(0xffffffffu, p1, 2);

        if (q == 0) {
            part[(wid >> 2) * 64 + r0] = p0;
            part[(wid >> 2) * 64 + r1] = p1;
        }
        __syncthreads();
        if (tid < 64)
            g_scores[tid * S_LEN + s] = part[tid] + part[64 + tid];
        __syncthreads();   // part + X safe to overwrite next iteration
    }
}

// ---------------------------------------------------------------------------
// masked softmax: 1024 threads/b, values cached in smem, single __expf pass
// ---------------------------------------------------------------------------
__global__ __launch_bounds__(1024) void softmax_kernel(const int* __restrict__ mask,
                                                       float* __restrict__ out) {
    __shared__ float ex[S_LEN];
    __shared__ float red[32];
    const int b = blockIdx.x, tid = threadIdx.x;
    const int wid = tid >> 5, lane = tid & 31;
    const float* sc = g_scores + b * S_LEN;
    const int*   mk = mask + b * S_LEN;

    float mx = -1e30f;
    #pragma unroll
    for (int s = tid; s < S_LEN; s += 1024) {
        float v = (mk[s] == 0) ? -1e10f : sc[s];
        ex[s] = v;
        mx = fmaxf(mx, v);
    }
    #pragma unroll
    for (int o = 16; o > 0; o >>= 1) mx = fmaxf(mx, __shfl_xor_sync(0xffffffffu, mx, o));
    if (lane == 0) red[wid] = mx;
    __syncthreads();
    if (wid == 0) {
        float m = red[lane];
        #pragma unroll
        for (int o = 16; o > 0; o >>= 1) m = fmaxf(m, __shfl_xor_sync(0xffffffffu, m, o));
        red[lane] = m;
    }
    __syncthreads();
    mx = red[0];

    float sum = 0.f;
    #pragma unroll
    for (int s = tid; s < S_LEN; s += 1024) {
        float e = __expf(ex[s] - mx);
        ex[s] = e;
        sum += e;
    }
    __syncthreads();
    #pragma unroll
    for (int o = 16; o > 0; o >>= 1) sum += __shfl_xor_sync(0xffffffffu, sum, o);
    if (lane == 0) red[wid] = sum;
    __syncthreads();
    if (wid == 0) {
        float m = red[lane];
        #pragma unroll
        for (int o = 16; o > 0; o >>= 1) m += __shfl_xor_sync(0xffffffffu, m, o);
        red[lane] = m;
    }
    __syncthreads();
    float inv = 1.f / red[0];

    #pragma unroll
    for (int s = tid; s < S_LEN; s += 1024)
        out[b * S_LEN + s] = ex[s] * inv;
}

// ---------------------------------------------------------------------------
extern "C" void kernel_launch(void* const* d_in, const int* in_sizes, int n_in,
                              void* d_out, int out_size) {
    const float* hidden = (const float*)d_in[0];
    const float* seq    = (const float*)d_in[1];
    const int*   mask   = (const int*)d_in[2];
    const float* W      = (const float*)d_in[3];
    const float* bias   = (const float*)d_in[4];
    const float* vw     = (const float*)d_in[5];
    float* out = (float*)d_out;

    cudaFuncSetAttribute(score_kernel, cudaFuncAttributeMaxDynamicSharedMemorySize, SMEM_BYTES);

    hproj_kernel<<<B_SZ, 256>>>(hidden, W, bias);
    wsplit_kernel<<<32, 256>>>(W);
    score_kernel<<<NCTA, 256, SMEM_BYTES>>>(seq, vw);
    softmax_kernel<<<B_SZ, 1024>>>(mask, out);
}

// round 7
// speedup vs baseline: 2.9811x; 1.1148x over previous
#include <cuda_runtime.h>
#include <cuda_bf16.h>
#include <math.h>
#include <stdint.h>

#define S_LEN 4096
#define B_SZ  64
#define EMB   128
#define DEC   128
#define FANIN 256
#define LDW   68            // u32 words per bf16 row: 136 bf16 = 128 data + 8 pad
#define ROWB  272           // bytes per padded bf16 row
#define NCTA  296           // persistent grid: 2 CTAs/SM x 148 SMs

// ---------------- scratch (no device allocation allowed) ----------------
__device__ float g_hproj[B_SZ * DEC];
__device__ float g_scores[B_SZ * S_LEN];
__device__ __align__(16) uint32_t g_we_hi[128 * LDW];
__device__ __align__(16) uint32_t g_we_lo[128 * LDW];
__device__ int g_sync;

// ---------------- helpers ----------------
__device__ __forceinline__ uint32_t smem_u32(const void* p) {
    uint32_t a;
    asm("{ .reg .u64 t; cvta.to.shared.u64 t, %1; cvt.u32.u64 %0, t; }" : "=r"(a) : "l"(p));
    return a;
}
#define LDSM4(r, a) \
    asm volatile("ldmatrix.sync.aligned.m8n8.x4.shared.b16 {%0,%1,%2,%3}, [%4];" \
        : "=r"((r)[0]), "=r"((r)[1]), "=r"((r)[2]), "=r"((r)[3]) : "r"(a))

#define MMA16816(c, a, b0, b1) \
    asm volatile("mma.sync.aligned.m16n8k16.row.col.f32.bf16.bf16.f32 " \
        "{%0,%1,%2,%3},{%4,%5,%6,%7},{%8,%9},{%0,%1,%2,%3};" \
        : "+f"((c)[0]), "+f"((c)[1]), "+f"((c)[2]), "+f"((c)[3]) \
        : "r"((a)[0]), "r"((a)[1]), "r"((a)[2]), "r"((a)[3]), "r"(b0), "r"(b1))

__device__ __forceinline__ float fast_tanh(float x) {
    float e = __expf(2.0f * x);
    return 1.0f - 2.0f / (e + 1.0f);
}

// ---------------------------------------------------------------------------
// Fused prep: blocks 0..63 -> h_proj rows; blocks 64..95 -> We hi/lo split.
// Block 0 also resets the sync counter (runs before score in-stream).
// ---------------------------------------------------------------------------
__global__ __launch_bounds__(256) void prep_kernel(const float* __restrict__ hidden,
                                                   const float* __restrict__ W,
                                                   const float* __restrict__ bias) {
    const int tid = threadIdx.x;
    if (blockIdx.x == 0 && tid == 0) g_sync = 0;

    if (blockIdx.x < B_SZ) {
        __shared__ float h[DEC];
        const int b = blockIdx.x;
        const int wid = tid >> 5, lane = tid & 31;
        if (tid < DEC) h[tid] = hidden[b * DEC + tid];
        __syncthreads();
        #pragma unroll
        for (int i = 0; i < 16; i++) {
            int d = wid * 16 + i;
            const float* w = W + d * FANIN;
            float sum = 0.f;
            #pragma unroll
            for (int e = lane; e < DEC; e += 32) sum = fmaf(h[e], w[e], sum);
            #pragma unroll
            for (int o = 16; o > 0; o >>= 1) sum += __shfl_xor_sync(0xffffffffu, sum, o);
            if (lane == 0) g_hproj[b * DEC + d] = sum + bias[d];
        }
    } else {
        int idx = (blockIdx.x - B_SZ) * 256 + tid;   // 8192 bf16x2 words
        int n  = idx >> 6;
        int kp = idx & 63;
        float x0 = W[n * FANIN + DEC + 2 * kp];
        float x1 = W[n * FANIN + DEC + 2 * kp + 1];
        uint32_t hi, lo;
        asm("cvt.rn.bf16x2.f32 %0, %1, %2;" : "=r"(hi) : "f"(x1), "f"(x0));
        float e0 = x0 - __uint_as_float(hi << 16);
        float e1 = x1 - __uint_as_float(hi & 0xffff0000u);
        asm("cvt.rn.bf16x2.f32 %0, %1, %2;" : "=r"(lo) : "f"(e1), "f"(e0));
        g_we_hi[n * LDW + kp] = hi;
        g_we_lo[n * LDW + kp] = lo;
    }
}

// ---------------------------------------------------------------------------
// persistent score kernel + fused softmax
// ---------------------------------------------------------------------------
#define OFF_V    0
#define OFF_PART 512
#define OFF_BHI  1024
#define OFF_BLO  (OFF_BHI + 34816)
#define OFF_XHI  (OFF_BLO + 34816)
#define OFF_XLO  (OFF_XHI + 17408)
#define SMEM_BYTES (OFF_XLO + 17408)   // 105472

extern __shared__ char smem[];

__global__ __launch_bounds__(256, 2) void score_kernel(const float* __restrict__ seq,
                                                       const float* __restrict__ vw,
                                                       const int* __restrict__ mask,
                                                       float* __restrict__ out) {
    const int tid  = threadIdx.x;
    const int wid  = tid >> 5;
    const int lane = tid & 31;

    // ---- one-time staging: We hi/lo + v ----
    {
        const int4* sh = (const int4*)g_we_hi;
        const int4* sl = (const int4*)g_we_lo;
        int4* dh = (int4*)(smem + OFF_BHI);
        int4* dl = (int4*)(smem + OFF_BLO);
        for (int i = tid; i < 2176; i += 256) { dh[i] = sh[i]; dl[i] = sl[i]; }
    }
    if (tid < 128) ((float*)(smem + OFF_V))[tid] = vw[tid];

    // ---- loop-invariant per-thread state ----
    const int mbase = (wid & 3) * 16;
    const int nbase = (wid >> 2) * 64;
    const int j = lane >> 3, r = lane & 7;
    const int q  = lane & 3;
    const int r0 = mbase + (lane >> 2), r1 = r0 + 8;

    // h_proj values this thread needs -> registers (acc init)
    float hp[8][4];
    #pragma unroll
    for (int nt = 0; nt < 8; nt++) {
        int c0 = nbase + nt * 8 + 2 * q;
        hp[nt][0] = g_hproj[r0 * DEC + c0];
        hp[nt][1] = g_hproj[r0 * DEC + c0 + 1];
        hp[nt][2] = g_hproj[r1 * DEC + c0];
        hp[nt][3] = g_hproj[r1 * DEC + c0 + 1];
    }

    const uint32_t a_hi = smem_u32(smem + OFF_XHI)
                        + (uint32_t)(mbase + r + 8 * (j & 1)) * ROWB + (uint32_t)(j >> 1) * 16;
    const uint32_t a_lo = a_hi + 17408;
    const uint32_t b_hi = smem_u32(smem + OFF_BHI)
                        + (uint32_t)(nbase + (j >> 1) * 8 + r) * ROWB + (uint32_t)(j & 1) * 16;
    const uint32_t b_lo = b_hi + 34816;

    float* part = (float*)(smem + OFF_PART);
    const float* vs = (const float*)(smem + OFF_V);

    // ---- prologue: prefetch first X tile into registers ----
    float4 xr[8];
    if (blockIdx.x < S_LEN) {
        const float4* src = (const float4*)(seq + (size_t)blockIdx.x * B_SZ * EMB);
        #pragma unroll
        for (int ii = 0; ii < 8; ii++) xr[ii] = src[tid + ii * 256];
    }
    __syncthreads();

    for (int s = blockIdx.x; s < S_LEN; s += NCTA) {
        // ---- convert prefetched registers -> bf16 hi/lo smem ----
        #pragma unroll
        for (int ii = 0; ii < 8; ii++) {
            int i = tid + ii * 256;
            float4 x = xr[ii];
            int row = i >> 5, c4 = i & 31;
            uint32_t h0, h1, l0, l1;
            asm("cvt.rn.bf16x2.f32 %0, %1, %2;" : "=r"(h0) : "f"(x.y), "f"(x.x));
            asm("cvt.rn.bf16x2.f32 %0, %1, %2;" : "=r"(h1) : "f"(x.w), "f"(x.z));
            float e0 = x.x - __uint_as_float(h0 << 16);
            float e1 = x.y - __uint_as_float(h0 & 0xffff0000u);
            float e2 = x.z - __uint_as_float(h1 << 16);
            float e3 = x.w - __uint_as_float(h1 & 0xffff0000u);
            asm("cvt.rn.bf16x2.f32 %0, %1, %2;" : "=r"(l0) : "f"(e1), "f"(e0));
            asm("cvt.rn.bf16x2.f32 %0, %1, %2;" : "=r"(l1) : "f"(e3), "f"(e2));
            char* px = smem + OFF_XHI + row * ROWB + c4 * 8;
            *(uint2*)px = make_uint2(h0, h1);
            *(uint2*)(px + 17408) = make_uint2(l0, l1);
        }
        __syncthreads();

        // ---- prefetch next tile while MMA runs ----
        int snext = s + NCTA;
        if (snext < S_LEN) {
            const float4* srcn = (const float4*)(seq + (size_t)snext * B_SZ * EMB);
            #pragma unroll
            for (int ii = 0; ii < 8; ii++) xr[ii] = srcn[tid + ii * 256];
        }

        // ---- GEMM: acc = hp + Ahi*Bhi + Ahi*Blo + Alo*Bhi ----
        float acc[8][4];
        #pragma unroll
        for (int nt = 0; nt < 8; nt++)
            #pragma unroll
            for (int qq = 0; qq < 4; qq++) acc[nt][qq] = hp[nt][qq];

        #pragma unroll
        for (int k = 0; k < 8; k++) {
            uint32_t ah[4], al[4];
            LDSM4(ah, a_hi + k * 32);
            LDSM4(al, a_lo + k * 32);
            #pragma unroll
            for (int p = 0; p < 4; p++) {
                uint32_t bh[4], bl[4];
                uint32_t boff = (uint32_t)p * (16 * ROWB) + (uint32_t)k * 32;
                LDSM4(bh, b_hi + boff);
                LDSM4(bl, b_lo + boff);
                MMA16816(acc[2 * p],     ah, bh[0], bh[1]);
                MMA16816(acc[2 * p],     ah, bl[0], bl[1]);
                MMA16816(acc[2 * p],     al, bh[0], bh[1]);
                MMA16816(acc[2 * p + 1], ah, bh[2], bh[3]);
                MMA16816(acc[2 * p + 1], ah, bl[2], bl[3]);
                MMA16816(acc[2 * p + 1], al, bh[2], bh[3]);
            }
        }

        // ---- epilogue: tanh + v-dot + quad reduce ----
        float p0 = 0.f, p1 = 0.f;
        #pragma unroll
        for (int nt = 0; nt < 8; nt++) {
            int c0 = nbase + nt * 8 + 2 * q;
            float v0 = vs[c0], v1 = vs[c0 + 1];
            p0 = fmaf(v0, fast_tanh(acc[nt][0]), p0);
            p0 = fmaf(v1, fast_tanh(acc[nt][1]), p0);
            p1 = fmaf(v0, fast_tanh(acc[nt][2]), p1);
            p1 = fmaf(v1, fast_tanh(acc[nt][3]), p1);
        }
        p0 += __shfl_xor_sync(0xffffffffu, p0, 1);
        p0 += __shfl_xor_sync(0xffffffffu, p0, 2);
        p1 += __shfl_xor_sync(0xffffffffu, p1, 1);
        p1 += __shfl_xor_sync(0xffffffffu, p1, 2);

        if (q == 0) {
            part[(wid >> 2) * 64 + r0] = p0;
            part[(wid >> 2) * 64 + r1] = p1;
        }
        __syncthreads();
        if (tid < 64)
            g_scores[tid * S_LEN + s] = part[tid] + part[64 + tid];
        __syncthreads();
    }

    // ================= fused softmax (grid-wide sync via counter) ==========
    __threadfence();
    if (tid == 0) atomicAdd(&g_sync, 1);
    if (blockIdx.x >= B_SZ) return;

    if (tid == 0) {
        int v;
        do {
            asm volatile("ld.acquire.gpu.s32 %0, [%1];" : "=r"(v) : "l"(&g_sync) : "memory");
        } while (v < NCTA);
    }
    __syncthreads();

    float* ex = (float*)smem;            // 16 KB, smem now free
    __shared__ float red[8];
    const int b = blockIdx.x;
    const float* sc = g_scores + b * S_LEN;
    const int*   mk = mask + b * S_LEN;

    float mx = -1e30f;
    #pragma unroll
    for (int i = 0; i < 16; i++) {
        int s = tid + i * 256;
        float v = (mk[s] == 0) ? -1e10f : sc[s];
        ex[s] = v;
        mx = fmaxf(mx, v);
    }
    #pragma unroll
    for (int o = 16; o > 0; o >>= 1) mx = fmaxf(mx, __shfl_xor_sync(0xffffffffu, mx, o));
    if (lane == 0) red[wid] = mx;
    __syncthreads();
    if (tid < 8) {
        float m = red[tid];
        #pragma unroll
        for (int o = 4; o > 0; o >>= 1) m = fmaxf(m, __shfl_xor_sync(0xffu, m, o));
        red[tid] = m;
    }
    __syncthreads();
    mx = red[0];

    float sum = 0.f;
    #pragma unroll
    for (int i = 0; i < 16; i++) {
        int s = tid + i * 256;
        float e = __expf(ex[s] - mx);
        ex[s] = e;
        sum += e;
    }
    #pragma unroll
    for (int o = 16; o > 0; o >>= 1) sum += __shfl_xor_sync(0xffffffffu, sum, o);
    __syncthreads();
    if (lane == 0) red[wid] = sum;
    __syncthreads();
    if (tid < 8) {
        float m = red[tid];
        #pragma unroll
        for (int o = 4; o > 0; o >>= 1) m += __shfl_xor_sync(0xffu, m, o);
        red[tid] = m;
    }
    __syncthreads();
    float inv = 1.f / red[0];

    #pragma unroll
    for (int i = 0; i < 16; i++) {
        int s = tid + i * 256;
        out[b * S_LEN + s] = ex[s] * inv;
    }
}

// ---------------------------------------------------------------------------
extern "C" void kernel_launch(void* const* d_in, const int* in_sizes, int n_in,
                              void* d_out, int out_size) {
    const float* hidden = (const float*)d_in[0];
    const float* seq    = (const float*)d_in[1];
    const int*   mask   = (const int*)d_in[2];
    const float* W      = (const float*)d_in[3];
    const float* bias   = (const float*)d_in[4];
    const float* vw     = (const float*)d_in[5];
    float* out = (float*)d_out;

    cudaFuncSetAttribute(score_kernel, cudaFuncAttributeMaxDynamicSharedMemorySize, SMEM_BYTES);

    prep_kernel<<<96, 256>>>(hidden, W, bias);
    score_kernel<<<NCTA, 256, SMEM_BYTES>>>(seq, vw, mask, out);
}

// round 9
// speedup vs baseline: 3.9264x; 1.3171x over previous
#include <cuda_runtime.h>
#include <cuda_fp16.h>
#include <math.h>
#include <stdint.h>

#define S_LEN 4096
#define B_SZ  64
#define EMB   128
#define DEC   128
#define FANIN 256
#define LDW   68            // u32 words per fp16 row: 136 halfs = 128 data + 8 pad
#define ROWB  272           // bytes per padded fp16 row
#define NCTA  296           // persistent grid: 2 CTAs/SM x 148 SMs

// ---------------- scratch (no device allocation allowed) ----------------
__device__ float g_hproj[B_SZ * DEC];
__device__ float g_scores[B_SZ * S_LEN];
__device__ __align__(16) uint32_t g_we_hi[128 * LDW];   // We hi fp16, [n][k] padded
__device__ __align__(16) uint32_t g_we_lo[128 * LDW];   // We residual fp16
__device__ int g_sync;

// ---------------- helpers ----------------
__device__ __forceinline__ uint32_t smem_u32(const void* p) {
    uint32_t a;
    asm("{ .reg .u64 t; cvta.to.shared.u64 t, %1; cvt.u32.u64 %0, t; }" : "=r"(a) : "l"(p));
    return a;
}
#define LDSM4(r, a) \
    asm volatile("ldmatrix.sync.aligned.m8n8.x4.shared.b16 {%0,%1,%2,%3}, [%4];" \
        : "=r"((r)[0]), "=r"((r)[1]), "=r"((r)[2]), "=r"((r)[3]) : "r"(a))

#define MMA16816(c, a, b0, b1) \
    asm volatile("mma.sync.aligned.m16n8k16.row.col.f32.f16.f16.f32 " \
        "{%0,%1,%2,%3},{%4,%5,%6,%7},{%8,%9},{%0,%1,%2,%3};" \
        : "+f"((c)[0]), "+f"((c)[1]), "+f"((c)[2]), "+f"((c)[3]) \
        : "r"((a)[0]), "r"((a)[1]), "r"((a)[2]), "r"((a)[3]), "r"(b0), "r"(b1))

__device__ __forceinline__ float fast_tanh(float x) {
    float e = __expf(2.0f * x);
    return 1.0f - 2.0f / (e + 1.0f);
}
__device__ __forceinline__ uint32_t pack_h2(float lo, float hi) {
    uint32_t w;
    asm("cvt.rn.f16x2.f32 %0, %1, %2;" : "=r"(w) : "f"(hi), "f"(lo));  // lo -> low half
    return w;
}
__device__ __forceinline__ float h2_low(uint32_t w)  { return __half2float(__ushort_as_half((unsigned short)(w & 0xffff))); }
__device__ __forceinline__ float h2_high(uint32_t w) { return __half2float(__ushort_as_half((unsigned short)(w >> 16))); }

// ---------------------------------------------------------------------------
// Fused prep: blocks 0..63 -> h_proj rows; blocks 64..95 -> We hi/lo fp16 split.
// ---------------------------------------------------------------------------
__global__ __launch_bounds__(256) void prep_kernel(const float* __restrict__ hidden,
                                                   const float* __restrict__ W,
                                                   const float* __restrict__ bias) {
    const int tid = threadIdx.x;
    if (blockIdx.x == 0 && tid == 0) g_sync = 0;

    if (blockIdx.x < B_SZ) {
        __shared__ float h[DEC];
        const int b = blockIdx.x;
        const int wid = tid >> 5, lane = tid & 31;
        if (tid < DEC) h[tid] = hidden[b * DEC + tid];
        __syncthreads();
        #pragma unroll
        for (int i = 0; i < 16; i++) {
            int d = wid * 16 + i;
            const float* w = W + d * FANIN;
            float sum = 0.f;
            #pragma unroll
            for (int e = lane; e < DEC; e += 32) sum = fmaf(h[e], w[e], sum);
            #pragma unroll
            for (int o = 16; o > 0; o >>= 1) sum += __shfl_xor_sync(0xffffffffu, sum, o);
            if (lane == 0) g_hproj[b * DEC + d] = sum + bias[d];
        }
    } else {
        int idx = (blockIdx.x - B_SZ) * 256 + tid;   // 8192 f16x2 words
        int n  = idx >> 6;
        int kp = idx & 63;
        float x0 = W[n * FANIN + DEC + 2 * kp];
        float x1 = W[n * FANIN + DEC + 2 * kp + 1];
        uint32_t hi = pack_h2(x0, x1);
        float l0 = x0 - h2_low(hi);
        float l1 = x1 - h2_high(hi);
        g_we_hi[n * LDW + kp] = hi;
        g_we_lo[n * LDW + kp] = pack_h2(l0, l1);
    }
}

// ---------------------------------------------------------------------------
// persistent score kernel + fused softmax.
// warp = (m-pair mp = wid&1, n-quarter nq = wid>>1):
//   m-tiles {2mp, 2mp+1} (rows mp*32..mp*32+31), cols nq*32..nq*32+31.
// D = hp + A*(Bh + Bl), A single fp16.
// ---------------------------------------------------------------------------
#define OFF_V    0
#define OFF_PART 512
#define OFF_BHI  2048
#define OFF_BLO  (OFF_BHI + 34816)
#define OFF_XHI  (OFF_BLO + 34816)
#define SMEM_BYTES (OFF_XHI + 17408)   // 89088

extern __shared__ char smem[];

__global__ __launch_bounds__(256, 2) void score_kernel(const float* __restrict__ seq,
                                                       const float* __restrict__ vw,
                                                       const int* __restrict__ mask,
                                                       float* __restrict__ out) {
    const int tid  = threadIdx.x;
    const int wid  = tid >> 5;
    const int lane = tid & 31;

    // ---- one-time staging: We hi/lo + v ----
    {
        const int4* sh = (const int4*)g_we_hi;
        const int4* sl = (const int4*)g_we_lo;
        int4* dh = (int4*)(smem + OFF_BHI);
        int4* dl = (int4*)(smem + OFF_BLO);
        for (int i = tid; i < 2176; i += 256) { dh[i] = sh[i]; dl[i] = sl[i]; }
    }
    if (tid < 128) ((float*)(smem + OFF_V))[tid] = vw[tid];

    // ---- loop-invariant per-thread state ----
    const int mp = wid & 1;          // m-pair: rows mp*32 .. mp*32+31
    const int nq = wid >> 1;         // n-quarter: cols nq*32 .. nq*32+31
    const int j = lane >> 3, r = lane & 7;
    const int q  = lane & 3;
    const int rbase = mp * 32 + (lane >> 2);   // mt-local row pattern

    // h_proj -> registers (acc init). acc[i][nt][*]: i = m-tile in pair, nt = n8.
    float hp[2][4][4];
    #pragma unroll
    for (int i = 0; i < 2; i++) {
        int ra = mp * 32 + i * 16 + (lane >> 2);
        #pragma unroll
        for (int nt = 0; nt < 4; nt++) {
            int c0 = nq * 32 + nt * 8 + 2 * q;
            hp[i][nt][0] = g_hproj[ra * DEC + c0];
            hp[i][nt][1] = g_hproj[ra * DEC + c0 + 1];
            hp[i][nt][2] = g_hproj[(ra + 8) * DEC + c0];
            hp[i][nt][3] = g_hproj[(ra + 8) * DEC + c0 + 1];
        }
    }

    const uint32_t a0_ad = smem_u32(smem + OFF_XHI)
                         + (uint32_t)(mp * 32 + r + 8 * (j & 1)) * ROWB + (uint32_t)(j >> 1) * 16;
    const uint32_t a1_ad = a0_ad + 16 * ROWB;
    const uint32_t b_hi  = smem_u32(smem + OFF_BHI)
                         + (uint32_t)(nq * 32 + (j >> 1) * 8 + r) * ROWB + (uint32_t)(j & 1) * 16;
    const uint32_t b_lo  = b_hi + 34816;

    float* part = (float*)(smem + OFF_PART);
    const float* vs = (const float*)(smem + OFF_V);

    // ---- prologue: prefetch first X tile into registers ----
    float4 xr[8];
    {
        const float4* src = (const float4*)(seq + (size_t)blockIdx.x * B_SZ * EMB);
        #pragma unroll
        for (int ii = 0; ii < 8; ii++) xr[ii] = src[tid + ii * 256];
    }
    __syncthreads();

    for (int s = blockIdx.x; s < S_LEN; s += NCTA) {
        // ---- convert prefetched registers -> fp16 smem (single precision level) ----
        #pragma unroll
        for (int ii = 0; ii < 8; ii++) {
            int i = tid + ii * 256;
            float4 x = xr[ii];
            int row = i >> 5, c4 = i & 31;
            uint32_t h0 = pack_h2(x.x, x.y);
            uint32_t h1 = pack_h2(x.z, x.w);
            *(uint2*)(smem + OFF_XHI + row * ROWB + c4 * 8) = make_uint2(h0, h1);
        }
        __syncthreads();

        // ---- prefetch next tile while MMA runs ----
        int snext = s + NCTA;
        if (snext < S_LEN) {
            const float4* srcn = (const float4*)(seq + (size_t)snext * B_SZ * EMB);
            #pragma unroll
            for (int ii = 0; ii < 8; ii++) xr[ii] = srcn[tid + ii * 256];
        }

        // ---- GEMM: acc = hp + A*Bh + A*Bl ----
        float acc[2][4][4];
        #pragma unroll
        for (int i = 0; i < 2; i++)
            #pragma unroll
            for (int nt = 0; nt < 4; nt++)
                #pragma unroll
                for (int qq = 0; qq < 4; qq++) acc[i][nt][qq] = hp[i][nt][qq];

        #pragma unroll
        for (int k = 0; k < 8; k++) {
            uint32_t a0[4], a1[4];
            LDSM4(a0, a0_ad + k * 32);
            LDSM4(a1, a1_ad + k * 32);
            #pragma unroll
            for (int p = 0; p < 2; p++) {
                uint32_t bh[4], bl[4];
                uint32_t boff = (uint32_t)p * (16 * ROWB) + (uint32_t)k * 32;
                LDSM4(bh, b_hi + boff);
                LDSM4(bl, b_lo + boff);
                int nt = p * 2;
                MMA16816(acc[0][nt],     a0, bh[0], bh[1]);
                MMA16816(acc[0][nt + 1], a0, bh[2], bh[3]);
                MMA16816(acc[1][nt],     a1, bh[0], bh[1]);
                MMA16816(acc[1][nt + 1], a1, bh[2], bh[3]);
                MMA16816(acc[0][nt],     a0, bl[0], bl[1]);
                MMA16816(acc[0][nt + 1], a0, bl[2], bl[3]);
                MMA16816(acc[1][nt],     a1, bl[0], bl[1]);
                MMA16816(acc[1][nt + 1], a1, bl[2], bl[3]);
            }
        }

        // ---- epilogue: tanh + v-dot + quad reduce ----
        #pragma unroll
        for (int i = 0; i < 2; i++) {
            float p0 = 0.f, p1 = 0.f;
            #pragma unroll
            for (int nt = 0; nt < 4; nt++) {
                int c0 = nq * 32 + nt * 8 + 2 * q;
                float v0 = vs[c0], v1 = vs[c0 + 1];
                p0 = fmaf(v0, fast_tanh(acc[i][nt][0]), p0);
                p0 = fmaf(v1, fast_tanh(acc[i][nt][1]), p0);
                p1 = fmaf(v0, fast_tanh(acc[i][nt][2]), p1);
                p1 = fmaf(v1, fast_tanh(acc[i][nt][3]), p1);
            }
            p0 += __shfl_xor_sync(0xffffffffu, p0, 1);
            p0 += __shfl_xor_sync(0xffffffffu, p0, 2);
            p1 += __shfl_xor_sync(0xffffffffu, p1, 1);
            p1 += __shfl_xor_sync(0xffffffffu, p1, 2);
            if (q == 0) {
                int ra = mp * 32 + i * 16 + (lane >> 2);
                part[nq * 64 + ra] = p0;
                part[nq * 64 + ra + 8] = p1;
            }
        }
        __syncthreads();
        if (tid < 64)
            g_scores[tid * S_LEN + s] = (part[tid] + part[64 + tid])
                                      + (part[128 + tid] + part[192 + tid]);
        __syncthreads();
    }

    // ================= fused softmax (grid-wide sync via counter) ==========
    __threadfence();
    if (tid == 0) atomicAdd(&g_sync, 1);
    if (blockIdx.x >= B_SZ) return;

    if (tid == 0) {
        int v;
        do {
            asm volatile("ld.acquire.gpu.s32 %0, [%1];" : "=r"(v) : "l"(&g_sync) : "memory");
        } while (v < NCTA);
    }
    __syncthreads();

    float* ex = (float*)smem;            // 16 KB, smem now free
    __shared__ float red[8];
    const int b = blockIdx.x;
    const float* sc = g_scores + b * S_LEN;
    const int*   mk = mask + b * S_LEN;

    float mx = -1e30f;
    #pragma unroll
    for (int i = 0; i < 16; i++) {
        int s = tid + i * 256;
        float v = (mk[s] == 0) ? -1e10f : sc[s];
        ex[s] = v;
        mx = fmaxf(mx, v);
    }
    #pragma unroll
    for (int o = 16; o > 0; o >>= 1) mx = fmaxf(mx, __shfl_xor_sync(0xffffffffu, mx, o));
    if (lane == 0) red[wid] = mx;
    __syncthreads();
    if (tid < 8) {
        float m = red[tid];
        #pragma unroll
        for (int o = 4; o > 0; o >>= 1) m = fmaxf(m, __shfl_xor_sync(0xffu, m, o));
        red[tid] = m;
    }
    __syncthreads();
    mx = red[0];

    float sum = 0.f;
    #pragma unroll
    for (int i = 0; i < 16; i++) {
        int s = tid + i * 256;
        float e = __expf(ex[s] - mx);
        ex[s] = e;
        sum += e;
    }
    #pragma unroll
    for (int o = 16; o > 0; o >>= 1) sum += __shfl_xor_sync(0xffffffffu, sum, o);
    __syncthreads();
    if (lane == 0) red[wid] = sum;
    __syncthreads();
    if (tid < 8) {
        float m = red[tid];
        #pragma unroll
        for (int o = 4; o > 0; o >>= 1) m += __shfl_xor_sync(0xffu, m, o);
        red[tid] = m;
    }
    __syncthreads();
    float inv = 1.f / red[0];

    #pragma unroll
    for (int i = 0; i < 16; i++) {
        int s = tid + i * 256;
        out[b * S_LEN + s] = ex[s] * inv;
    }
}

// ---------------------------------------------------------------------------
extern "C" void kernel_launch(void* const* d_in, const int* in_sizes, int n_in,
                              void* d_out, int out_size) {
    const float* hidden = (const float*)d_in[0];
    const float* seq    = (const float*)d_in[1];
    const int*   mask   = (const int*)d_in[2];
    const float* W      = (const float*)d_in[3];
    const float* bias   = (const float*)d_in[4];
    const float* vw     = (const float*)d_in[5];
    float* out = (float*)d_out;

    cudaFuncSetAttribute(score_kernel, cudaFuncAttributeMaxDynamicSharedMemorySize, SMEM_BYTES);

    prep_kernel<<<96, 256>>>(hidden, W, bias);
    score_kernel<<<NCTA, 256, SMEM_BYTES>>>(seq, vw, mask, out);
}

// round 12
// speedup vs baseline: 6.1907x; 1.5767x over previous
#include <cuda_runtime.h>
#include <cuda_fp16.h>
#include <math.h>
#include <stdint.h>

#define S_LEN 4096
#define B_SZ  64
#define EMB   128
#define DEC   128
#define FANIN 256
#define LDW   68            // u32 words per fp16 row: 136 halfs = 128 data + 8 pad
#define ROWB  272           // bytes per padded fp16 row
#define NCTA  296           // persistent grid: 2 CTAs/SM x 148 SMs

// ---------------- scratch (no device allocation allowed) ----------------
__device__ float g_hproj[B_SZ * DEC];
__device__ float g_scores[B_SZ * S_LEN];
__device__ __align__(16) uint32_t g_we[128 * LDW];   // We fp16, [n][k] padded
__device__ int g_sync;

// ---------------- helpers ----------------
__device__ __forceinline__ uint32_t smem_u32(const void* p) {
    uint32_t a;
    asm("{ .reg .u64 t; cvta.to.shared.u64 t, %1; cvt.u32.u64 %0, t; }" : "=r"(a) : "l"(p));
    return a;
}
#define LDSM4(r, a) \
    asm volatile("ldmatrix.sync.aligned.m8n8.x4.shared.b16 {%0,%1,%2,%3}, [%4];" \
        : "=r"((r)[0]), "=r"((r)[1]), "=r"((r)[2]), "=r"((r)[3]) : "r"(a))

#define MMA16816(c, a, b0, b1) \
    asm volatile("mma.sync.aligned.m16n8k16.row.col.f32.f16.f16.f32 " \
        "{%0,%1,%2,%3},{%4,%5,%6,%7},{%8,%9},{%0,%1,%2,%3};" \
        : "+f"((c)[0]), "+f"((c)[1]), "+f"((c)[2]), "+f"((c)[3]) \
        : "r"((a)[0]), "r"((a)[1]), "r"((a)[2]), "r"((a)[3]), "r"(b0), "r"(b1))

__device__ __forceinline__ float tanh_approx(float x) {
    float t;
    asm("tanh.approx.f32 %0, %1;" : "=f"(t) : "f"(x));
    return t;
}
__device__ __forceinline__ uint32_t pack_h2(float lo, float hi) {
    uint32_t w;
    asm("cvt.rn.f16x2.f32 %0, %1, %2;" : "=r"(w) : "f"(hi), "f"(lo));  // lo -> low half
    return w;
}

// ---------------------------------------------------------------------------
// Fused prep: blocks 0..63 -> h_proj rows; blocks 64..95 -> We fp16 convert.
// ---------------------------------------------------------------------------
__global__ __launch_bounds__(256) void prep_kernel(const float* __restrict__ hidden,
                                                   const float* __restrict__ W,
                                                   const float* __restrict__ bias) {
    const int tid = threadIdx.x;
    if (blockIdx.x == 0 && tid == 0) g_sync = 0;

    if (blockIdx.x < B_SZ) {
        __shared__ float h[DEC];
        const int b = blockIdx.x;
        const int wid = tid >> 5, lane = tid & 31;
        if (tid < DEC) h[tid] = hidden[b * DEC + tid];
        __syncthreads();
        #pragma unroll
        for (int i = 0; i < 16; i++) {
            int d = wid * 16 + i;
            const float* w = W + d * FANIN;
            float sum = 0.f;
            #pragma unroll
            for (int e = lane; e < DEC; e += 32) sum = fmaf(h[e], w[e], sum);
            #pragma unroll
            for (int o = 16; o > 0; o >>= 1) sum += __shfl_xor_sync(0xffffffffu, sum, o);
            if (lane == 0) g_hproj[b * DEC + d] = sum + bias[d];
        }
    } else {
        int idx = (blockIdx.x - B_SZ) * 256 + tid;   // 8192 f16x2 words
        int n  = idx >> 6;
        int kp = idx & 63;
        float x0 = W[n * FANIN + DEC + 2 * kp];
        float x1 = W[n * FANIN + DEC + 2 * kp + 1];
        g_we[n * LDW + kp] = pack_h2(x0, x1);
    }
}

// ---------------------------------------------------------------------------
// persistent score kernel + fused softmax.
// warp = (m-pair mp = wid&1, n-quarter nq = wid>>1). Single fp16 product.
// X double-buffered in smem.
// ---------------------------------------------------------------------------
#define OFF_V    0
#define OFF_PART 512
#define OFF_B    2048
#define OFF_X0   (OFF_B + 34816)         // 36864
#define OFF_X1   (OFF_X0 + 17408)        // 54272
#define SMEM_BYTES (OFF_X1 + 17408)      // 71680

extern __shared__ char smem[];

__global__ __launch_bounds__(256, 2) void score_kernel(const float* __restrict__ seq,
                                                       const float* __restrict__ vw,
                                                       const int* __restrict__ mask,
                                                       float* __restrict__ out) {
    const int tid  = threadIdx.x;
    const int wid  = tid >> 5;
    const int lane = tid & 31;

    // ---- one-time staging: We + v ----
    {
        const int4* sh = (const int4*)g_we;
        int4* dh = (int4*)(smem + OFF_B);
        for (int i = tid; i < 2176; i += 256) dh[i] = sh[i];
    }
    if (tid < 128) ((float*)(smem + OFF_V))[tid] = vw[tid];

    // ---- loop-invariant per-thread state ----
    const int mp = wid & 1;          // m-pair: rows mp*32 .. mp*32+31
    const int nq = wid >> 1;         // n-quarter: cols nq*32 .. nq*32+31
    const int j = lane >> 3, r = lane & 7;
    const int q  = lane & 3;

    // h_proj -> registers (acc init). acc[i][nt][*]: i = m-tile in pair, nt = n8.
    float hp[2][4][4];
    #pragma unroll
    for (int i = 0; i < 2; i++) {
        int ra = mp * 32 + i * 16 + (lane >> 2);
        #pragma unroll
        for (int nt = 0; nt < 4; nt++) {
            int c0 = nq * 32 + nt * 8 + 2 * q;
            hp[i][nt][0] = g_hproj[ra * DEC + c0];
            hp[i][nt][1] = g_hproj[ra * DEC + c0 + 1];
            hp[i][nt][2] = g_hproj[(ra + 8) * DEC + c0];
            hp[i][nt][3] = g_hproj[(ra + 8) * DEC + c0 + 1];
        }
    }

    const uint32_t a_base = smem_u32(smem + OFF_X0)
                          + (uint32_t)(mp * 32 + r + 8 * (j & 1)) * ROWB + (uint32_t)(j >> 1) * 16;
    const uint32_t b_ad   = smem_u32(smem + OFF_B)
                          + (uint32_t)(nq * 32 + (j >> 1) * 8 + r) * ROWB + (uint32_t)(j & 1) * 16;

    float* part = (float*)(smem + OFF_PART);
    const float* vs = (const float*)(smem + OFF_V);

    // ---- prologue: prefetch first X tile into registers ----
    float4 xr[8];
    {
        const float4* src = (const float4*)(seq + (size_t)blockIdx.x * B_SZ * EMB);
        #pragma unroll
        for (int ii = 0; ii < 8; ii++) xr[ii] = src[tid + ii * 256];
    }
    __syncthreads();

    uint32_t parity = 0;
    for (int s = blockIdx.x; s < S_LEN; s += NCTA) {
        const uint32_t xoff = parity ? 17408u : 0u;

        // ---- convert prefetched registers -> fp16 smem buffer[parity] ----
        #pragma unroll
        for (int ii = 0; ii < 8; ii++) {
            int i = tid + ii * 256;
            float4 x = xr[ii];
            int row = i >> 5, c4 = i & 31;
            uint32_t h0 = pack_h2(x.x, x.y);
            uint32_t h1 = pack_h2(x.z, x.w);
            *(uint2*)(smem + OFF_X0 + xoff + row * ROWB + c4 * 8) = make_uint2(h0, h1);
        }
        __syncthreads();

        // ---- prefetch next tile while MMA runs ----
        int snext = s + NCTA;
        if (snext < S_LEN) {
            const float4* srcn = (const float4*)(seq + (size_t)snext * B_SZ * EMB);
            #pragma unroll
            for (int ii = 0; ii < 8; ii++) xr[ii] = srcn[tid + ii * 256];
        }

        // ---- GEMM: acc = hp + A*B (single fp16 product) ----
        float acc[2][4][4];
        #pragma unroll
        for (int i = 0; i < 2; i++)
            #pragma unroll
            for (int nt = 0; nt < 4; nt++)
                #pragma unroll
                for (int qq = 0; qq < 4; qq++) acc[i][nt][qq] = hp[i][nt][qq];

        const uint32_t a_ad = a_base + xoff;
        #pragma unroll
        for (int k = 0; k < 8; k++) {
            uint32_t a0[4], a1[4];
            LDSM4(a0, a_ad + k * 32);
            LDSM4(a1, a_ad + 16 * ROWB + k * 32);
            #pragma unroll
            for (int p = 0; p < 2; p++) {
                uint32_t bh[4];
                LDSM4(bh, b_ad + (uint32_t)p * (16 * ROWB) + (uint32_t)k * 32);
                int nt = p * 2;
                MMA16816(acc[0][nt],     a0, bh[0], bh[1]);
                MMA16816(acc[0][nt + 1], a0, bh[2], bh[3]);
                MMA16816(acc[1][nt],     a1, bh[0], bh[1]);
                MMA16816(acc[1][nt + 1], a1, bh[2], bh[3]);
            }
        }

        // ---- epilogue: tanh.approx + v-dot + quad reduce ----
        #pragma unroll
        for (int i = 0; i < 2; i++) {
            float p0 = 0.f, p1 = 0.f;
            #pragma unroll
            for (int nt = 0; nt < 4; nt++) {
                int c0 = nq * 32 + nt * 8 + 2 * q;
                float v0 = vs[c0], v1 = vs[c0 + 1];
                p0 = fmaf(v0, tanh_approx(acc[i][nt][0]), p0);
                p0 = fmaf(v1, tanh_approx(acc[i][nt][1]), p0);
                p1 = fmaf(v0, tanh_approx(acc[i][nt][2]), p1);
                p1 = fmaf(v1, tanh_approx(acc[i][nt][3]), p1);
            }
            p0 += __shfl_xor_sync(0xffffffffu, p0, 1);
            p0 += __shfl_xor_sync(0xffffffffu, p0, 2);
            p1 += __shfl_xor_sync(0xffffffffu, p1, 1);
            p1 += __shfl_xor_sync(0xffffffffu, p1, 2);
            if (q == 0) {
                int ra = mp * 32 + i * 16 + (lane >> 2);
                part[nq * 64 + ra] = p0;
                part[nq * 64 + ra + 8] = p1;
            }
        }
        __syncthreads();
        if (tid < 64)
            g_scores[tid * S_LEN + s] = (part[tid] + part[64 + tid])
                                      + (part[128 + tid] + part[192 + tid]);
        parity ^= 1u;   // convert of next tile goes to the other buffer (no 3rd sync)
    }

    // ================= fused softmax (grid-wide sync via counter) ==========
    __threadfence();
    if (tid == 0) atomicAdd(&g_sync, 1);
    if (blockIdx.x >= B_SZ) return;

    if (tid == 0) {
        int v;
        do {
            asm volatile("ld.acquire.gpu.s32 %0, [%1];" : "=r"(v) : "l"(&g_sync) : "memory");
        } while (v < NCTA);
    }
    __syncthreads();

    float* ex = (float*)smem;            // 16 KB, smem now free
    __shared__ float red[8];
    const int b = blockIdx.x;
    const float* sc = g_scores + b * S_LEN;
    const int*   mk = mask + b * S_LEN;

    float mx = -1e30f;
    #pragma unroll
    for (int i = 0; i < 16; i++) {
        int s = tid + i * 256;
        float v = (mk[s] == 0) ? -1e10f : sc[s];
        ex[s] = v;
        mx = fmaxf(mx, v);
    }
    #pragma unroll
    for (int o = 16; o > 0; o >>= 1) mx = fmaxf(mx, __shfl_xor_sync(0xffffffffu, mx, o));
    if (lane == 0) red[wid] = mx;
    __syncthreads();
    if (tid < 8) {
        float m = red[tid];
        #pragma unroll
        for (int o = 4; o > 0; o >>= 1) m = fmaxf(m, __shfl_xor_sync(0xffu, m, o));
        red[tid] = m;
    }
    __syncthreads();
    mx = red[0];

    float sum = 0.f;
    #pragma unroll
    for (int i = 0; i < 16; i++) {
        int s = tid + i * 256;
        float e = __expf(ex[s] - mx);
        ex[s] = e;
        sum += e;
    }
    #pragma unroll
    for (int o = 16; o > 0; o >>= 1) sum += __shfl_xor_sync(0xffffffffu, sum, o);
    __syncthreads();
    if (lane == 0) red[wid] = sum;
    __syncthreads();
    if (tid < 8) {
        float m = red[tid];
        #pragma unroll
        for (int o = 4; o > 0; o >>= 1) m += __shfl_xor_sync(0xffu, m, o);
        red[tid] = m;
    }
    __syncthreads();
    float inv = 1.f / red[0];

    #pragma unroll
    for (int i = 0; i < 16; i++) {
        int s = tid + i * 256;
        out[b * S_LEN + s] = ex[s] * inv;
    }
}

// ---------------------------------------------------------------------------
extern "C" void kernel_launch(void* const* d_in, const int* in_sizes, int n_in,
                              void* d_out, int out_size) {
    const float* hidden = (const float*)d_in[0];
    const float* seq    = (const float*)d_in[1];
    const int*   mask   = (const int*)d_in[2];
    const float* W      = (const float*)d_in[3];
    const float* bias   = (const float*)d_in[4];
    const float* vw     = (const float*)d_in[5];
    float* out = (float*)d_out;

    cudaFuncSetAttribute(score_kernel, cudaFuncAttributeMaxDynamicSharedMemorySize, SMEM_BYTES);

    prep_kernel<<<96, 256>>>(hidden, W, bias);
    score_kernel<<<NCTA, 256, SMEM_BYTES>>>(seq, vw, mask, out);
}